// round 8
// baseline (speedup 1.0000x reference)
#include <cuda_runtime.h>

// DCT band decomposition: x[16,3,512,512] f32 -> (low, mid, high) concatenated.
// Each thread processes TWO vertically adjacent 8x8 blocks with all math in
// packed f32x2 (FFMA2): half the FMA instructions, 2x ILP per warp.

namespace {
constexpr int H = 512, W = 512;
constexpr int NPIX = 16 * 3 * H * W;             // 12582912
constexpr int NBLK = 16 * 3 * (H / 8) * (W / 8); // 196608
constexpr int TPB  = 128;
constexpr int NTHREADS = NBLK / 2;               // 98304
}

typedef unsigned long long u64;

#define A4f 0.3535533905932738f
#define C1f 0.4903926402016152f
#define C2f 0.4619397662556434f
#define C3f 0.4157348061512726f
#define C5f 0.2777851165098011f
#define C6f 0.1913417161825449f
#define C7f 0.0975451610080641f

// Orthonormal 8-point DCT-II matrix (compile-time literals after unroll).
__host__ __device__ constexpr float Dv(int k, int t) {
    constexpr float m[8][8] = {
        { A4f,  A4f,  A4f,  A4f,  A4f,  A4f,  A4f,  A4f},
        { C1f,  C3f,  C5f,  C7f, -C7f, -C5f, -C3f, -C1f},
        { C2f,  C6f, -C6f, -C2f, -C2f, -C6f,  C6f,  C2f},
        { C3f, -C7f, -C1f, -C5f,  C5f,  C1f,  C7f, -C3f},
        { A4f, -A4f, -A4f,  A4f,  A4f, -A4f, -A4f,  A4f},
        { C5f, -C1f,  C7f,  C3f, -C3f, -C7f,  C1f, -C5f},
        { C6f, -C2f,  C2f, -C6f, -C6f,  C2f, -C2f,  C6f},
        { C7f, -C5f,  C3f, -C1f,  C1f, -C3f,  C5f, -C7f}
    };
    return m[k][t];
}

// Zigzag bands: low = zz<21 <=> k+l<=5 ; mid = 21<=zz<42 <=> 6<=k+l<=8 \ (1,7)
__host__ __device__ constexpr bool in_band(int band, int k, int l) {
    const int s = k + l;
    const bool low = (s <= 5);
    const bool mid = (s >= 6 && s <= 8) && !(k == 1 && l == 7);
    if (band == 0) return low;
    if (band == 1) return mid;
    return !low && !mid;
}
__host__ __device__ constexpr bool col_active(int band, int l) {
    bool a = false;
    for (int k = 0; k < 8; k++) if (in_band(band, k, l)) a = true;
    return a;
}

// ---- packed f32x2 primitives ----
__device__ __forceinline__ u64 F2(u64 a, u64 b, u64 c) {   // a*b + c
    u64 d; asm("fma.rn.f32x2 %0,%1,%2,%3;" : "=l"(d) : "l"(a), "l"(b), "l"(c));
    return d;
}
__device__ __forceinline__ u64 M2(u64 a, u64 b) {
    u64 d; asm("mul.rn.f32x2 %0,%1,%2;" : "=l"(d) : "l"(a), "l"(b));
    return d;
}
__device__ __forceinline__ u64 A2(u64 a, u64 b) {
    u64 d; asm("add.rn.f32x2 %0,%1,%2;" : "=l"(d) : "l"(a), "l"(b));
    return d;
}
// broadcast float constant -> packed {v,v} bit pattern (folds to immediate)
__host__ __device__ constexpr u64 pc(float v) {
    unsigned u = __builtin_bit_cast(unsigned, v);
    return ((u64)u << 32) | (u64)u;
}
__device__ __forceinline__ u64 S2(u64 a, u64 b) {   // a - b (exact via fma)
    return F2(b, pc(-1.0f), a);
}
__device__ __forceinline__ u64 pk(float lo, float hi) {
    u64 r; asm("mov.b64 %0,{%1,%2};" : "=l"(r) : "f"(lo), "f"(hi));
    return r;
}
__device__ __forceinline__ float2 up(u64 v) {
    float2 r; asm("mov.b64 {%0,%1},%2;" : "=f"(r.x), "=f"(r.y) : "l"(v));
    return r;
}

// Fast 8-point DCT-II on packed pairs, in place.
__device__ __forceinline__ void dct8p(u64 x[8]) {
    u64 e0 = A2(x[0], x[7]), e1 = A2(x[1], x[6]);
    u64 e2 = A2(x[2], x[5]), e3 = A2(x[3], x[4]);
    u64 o0 = S2(x[0], x[7]), o1 = S2(x[1], x[6]);
    u64 o2 = S2(x[2], x[5]), o3 = S2(x[3], x[4]);
    u64 f0 = A2(e0, e3), f1 = A2(e1, e2);
    u64 g0 = S2(e0, e3), g1 = S2(e1, e2);
    x[0] = M2(A2(f0, f1), pc(A4f));
    x[4] = M2(S2(f0, f1), pc(A4f));
    x[2] = F2(g0, pc(C2f),  M2(g1, pc(C6f)));
    x[6] = F2(g1, pc(-C2f), M2(g0, pc(C6f)));
    x[1] = F2(o0, pc(C1f), F2(o1, pc(C3f),  F2(o2, pc(C5f),  M2(o3, pc(C7f)))));
    x[3] = F2(o0, pc(C3f), F2(o1, pc(-C7f), F2(o2, pc(-C1f), M2(o3, pc(-C5f)))));
    x[5] = F2(o0, pc(C5f), F2(o1, pc(-C1f), F2(o2, pc(C7f),  M2(o3, pc(C3f)))));
    x[7] = F2(o0, pc(C7f), F2(o1, pc(-C5f), F2(o2, pc(C3f),  M2(o3, pc(-C1f)))));
}

// Stage 2 of masked IDCT + store: o[n] = sum_l y[l]*Dv(l,n), n/(7-n) symmetry.
// Unpacks pairs into the two blocks' rows.
template <int BAND>
__device__ __forceinline__ void idct_row_store(const u64 y[8],
                                               float* __restrict__ dA,
                                               float* __restrict__ dB)
{
    u64 o[8];
#pragma unroll
    for (int n = 0; n < 4; n++) {
        u64 E = 0ULL, O = 0ULL;
#pragma unroll
        for (int l = 0; l < 8; l += 2)
            if (col_active(BAND, l)) E = F2(y[l], pc(Dv(l, n)), E);
#pragma unroll
        for (int l = 1; l < 8; l += 2)
            if (col_active(BAND, l)) O = F2(y[l], pc(Dv(l, n)), O);
        o[n]     = A2(E, O);
        o[7 - n] = S2(E, O);
    }
    float2 u0 = up(o[0]), u1 = up(o[1]), u2 = up(o[2]), u3 = up(o[3]);
    float2 u4 = up(o[4]), u5 = up(o[5]), u6 = up(o[6]), u7 = up(o[7]);
    __stcs(reinterpret_cast<float4*>(dA),     make_float4(u0.x, u1.x, u2.x, u3.x));
    __stcs(reinterpret_cast<float4*>(dA + 4), make_float4(u4.x, u5.x, u6.x, u7.x));
    __stcs(reinterpret_cast<float4*>(dB),     make_float4(u0.y, u1.y, u2.y, u3.y));
    __stcs(reinterpret_cast<float4*>(dB + 4), make_float4(u4.y, u5.y, u6.y, u7.y));
}

// Masked inverse DCT of one band, row pairs (m, 7-m) via k-parity symmetry.
template <int BAND>
__device__ __forceinline__ void band_idct(const u64 C[8][8], u64 scl,
                                          float* __restrict__ dA,
                                          float* __restrict__ dB)
{
#pragma unroll
    for (int m = 0; m < 4; m++) {
        u64 yA[8], yB[8];
#pragma unroll
        for (int l = 0; l < 8; l++) {
            if (col_active(BAND, l)) {
                u64 se = 0ULL, so = 0ULL;
#pragma unroll
                for (int k = 0; k < 8; k += 2)
                    if (in_band(BAND, k, l)) se = F2(C[k][l], pc(Dv(k, m)), se);
#pragma unroll
                for (int k = 1; k < 8; k += 2)
                    if (in_band(BAND, k, l)) so = F2(C[k][l], pc(Dv(k, m)), so);
                yA[l] = M2(A2(se, so), scl);   // row m
                yB[l] = M2(S2(se, so), scl);   // row 7-m
            } else { yA[l] = 0ULL; yB[l] = 0ULL; }
        }
        idct_row_store<BAND>(yA, dA + (size_t)m * W,       dB + (size_t)m * W);
        idct_row_store<BAND>(yB, dA + (size_t)(7 - m) * W, dB + (size_t)(7 - m) * W);
    }
}

__global__ void __launch_bounds__(TPB, 4)
dct_decomp_kernel(const float* __restrict__ x,
                  const float* __restrict__ band_scale,
                  float* __restrict__ out)
{
    const int tid = blockIdx.x * TPB + threadIdx.x;   // [0, 98304)
    const int bw  = tid & 63;          // block col (coalesced across lanes)
    const int bhp = (tid >> 6) & 31;   // block-row PAIR
    const int bc  = tid >> 11;         // fused batch*chan 0..47

    const size_t baseA = ((size_t)bc * H + (size_t)bhp * 16) * W + (size_t)bw * 8;
    const size_t baseB = baseA + 8 * (size_t)W;
    const float* srcA = x + baseA;
    const float* srcB = x + baseB;

    const u64 s0p = pk(__ldg(band_scale + 0), __ldg(band_scale + 0));
    const u64 s1p = pk(__ldg(band_scale + 1), __ldg(band_scale + 1));
    const u64 s2p = pk(__ldg(band_scale + 2), __ldg(band_scale + 2));

    // ---- Load both 8x8 blocks (32 LDG.128, front-batched), pack pairs ----
    u64 C[8][8];
#pragma unroll
    for (int r = 0; r < 8; r++) {
        float4 a0 = __ldg(reinterpret_cast<const float4*>(srcA + (size_t)r * W));
        float4 b0 = __ldg(reinterpret_cast<const float4*>(srcA + (size_t)r * W + 4));
        float4 a1 = __ldg(reinterpret_cast<const float4*>(srcB + (size_t)r * W));
        float4 b1 = __ldg(reinterpret_cast<const float4*>(srcB + (size_t)r * W + 4));
        C[r][0] = pk(a0.x, a1.x); C[r][1] = pk(a0.y, a1.y);
        C[r][2] = pk(a0.z, a1.z); C[r][3] = pk(a0.w, a1.w);
        C[r][4] = pk(b0.x, b1.x); C[r][5] = pk(b0.y, b1.y);
        C[r][6] = pk(b0.z, b1.z); C[r][7] = pk(b0.w, b1.w);
    }

    // ---- Forward 2D DCT in place (both blocks at once) ----
#pragma unroll
    for (int t = 0; t < 8; t++) {      // column pass
        u64 col[8];
#pragma unroll
        for (int m = 0; m < 8; m++) col[m] = C[m][t];
        dct8p(col);
#pragma unroll
        for (int k = 0; k < 8; k++) C[k][t] = col[k];
    }
#pragma unroll
    for (int k = 0; k < 8; k++)        // row pass
        dct8p(C[k]);

    // ---- Three masked inverse DCTs ----
    band_idct<0>(C, s0p, out + baseA,                  out + baseB);
    band_idct<1>(C, s1p, out + (size_t)NPIX + baseA,   out + (size_t)NPIX + baseB);
    band_idct<2>(C, s2p, out + 2 * (size_t)NPIX + baseA, out + 2 * (size_t)NPIX + baseB);
}

extern "C" void kernel_launch(void* const* d_in, const int* in_sizes, int n_in,
                              void* d_out, int out_size)
{
    const float* x  = (const float*)d_in[0];
    const float* bs = (const float*)d_in[1];
    float* out = (float*)d_out;

    const int grid = NTHREADS / TPB;   // 768
    dct_decomp_kernel<<<grid, TPB>>>(x, bs, out);
}

// round 9
// speedup vs baseline: 1.2520x; 1.2520x over previous
#include <cuda_runtime.h>

// DCT band decomposition: x[16,3,512,512] f32 -> (low, mid, high) concatenated.
// One thread per 8x8 block. Butterfly forward DCT; band IDCTs exploit
// m/(7-m) and n/(7-n) cosine symmetry. DCT constants fold to FFMA immediates.
// Loads default-cached (input is L2-resident across graph replays);
// stores evict-first so the 151MB write stream doesn't flush the input.
// launch_bounds(128,8): force 64-reg cap -> 32 warps/SM; small spill tax
// is hidden by the added warps.

namespace {
constexpr int H = 512, W = 512;
constexpr int NPIX = 16 * 3 * H * W;             // 12582912
constexpr int NBLK = 16 * 3 * (H / 8) * (W / 8); // 196608
constexpr int TPB  = 128;
}

#define A4f 0.3535533905932738f
#define C1f 0.4903926402016152f
#define C2f 0.4619397662556434f
#define C3f 0.4157348061512726f
#define C5f 0.2777851165098011f
#define C6f 0.1913417161825449f
#define C7f 0.0975451610080641f

// Orthonormal 8-point DCT-II matrix (compile-time literals after unroll).
__host__ __device__ constexpr float Dv(int k, int t) {
    constexpr float m[8][8] = {
        { A4f,  A4f,  A4f,  A4f,  A4f,  A4f,  A4f,  A4f},
        { C1f,  C3f,  C5f,  C7f, -C7f, -C5f, -C3f, -C1f},
        { C2f,  C6f, -C6f, -C2f, -C2f, -C6f,  C6f,  C2f},
        { C3f, -C7f, -C1f, -C5f,  C5f,  C1f,  C7f, -C3f},
        { A4f, -A4f, -A4f,  A4f,  A4f, -A4f, -A4f,  A4f},
        { C5f, -C1f,  C7f,  C3f, -C3f, -C7f,  C1f, -C5f},
        { C6f, -C2f,  C2f, -C6f, -C6f,  C2f, -C2f,  C6f},
        { C7f, -C5f,  C3f, -C1f,  C1f, -C3f,  C5f, -C7f}
    };
    return m[k][t];
}

// Zigzag bands: low = zz<21 <=> k+l<=5 ; mid = 21<=zz<42 <=> 6<=k+l<=8 \ (1,7)
__host__ __device__ constexpr bool in_band(int band, int k, int l) {
    const int s = k + l;
    const bool low = (s <= 5);
    const bool mid = (s >= 6 && s <= 8) && !(k == 1 && l == 7);
    if (band == 0) return low;
    if (band == 1) return mid;
    return !low && !mid;
}
__host__ __device__ constexpr bool col_active(int band, int l) {
    bool a = false;
    for (int k = 0; k < 8; k++) if (in_band(band, k, l)) a = true;
    return a;
}

// Fast 8-point DCT-II (orthonormal) on 8 values in place.
__device__ __forceinline__ void dct8(float x[8]) {
    const float e0 = x[0] + x[7], e1 = x[1] + x[6], e2 = x[2] + x[5], e3 = x[3] + x[4];
    const float o0 = x[0] - x[7], o1 = x[1] - x[6], o2 = x[2] - x[5], o3 = x[3] - x[4];
    const float f0 = e0 + e3, f1 = e1 + e2;
    const float g0 = e0 - e3, g1 = e1 - e2;
    x[0] = A4f * (f0 + f1);
    x[4] = A4f * (f0 - f1);
    x[2] = fmaf(C2f, g0,  C6f * g1);
    x[6] = fmaf(C6f, g0, -C2f * g1);
    x[1] = fmaf(C1f, o0, fmaf( C3f, o1, fmaf( C5f, o2,  C7f * o3)));
    x[3] = fmaf(C3f, o0, fmaf(-C7f, o1, fmaf(-C1f, o2, -C5f * o3)));
    x[5] = fmaf(C5f, o0, fmaf(-C1f, o1, fmaf( C7f, o2,  C3f * o3)));
    x[7] = fmaf(C7f, o0, fmaf(-C5f, o1, fmaf( C3f, o2, -C1f * o3)));
}

// Stage 2 of masked IDCT: o[n] = sum_l y[l]*Dv(l,n) with n/(7-n) symmetry.
template <int BAND>
__device__ __forceinline__ void idct_row_store(const float y[8],
                                               float* __restrict__ dst)
{
    float o[8];
#pragma unroll
    for (int n = 0; n < 4; n++) {
        float E = 0.0f, O = 0.0f;
#pragma unroll
        for (int l = 0; l < 8; l += 2)
            if (col_active(BAND, l)) E = fmaf(y[l], Dv(l, n), E);
#pragma unroll
        for (int l = 1; l < 8; l += 2)
            if (col_active(BAND, l)) O = fmaf(y[l], Dv(l, n), O);
        o[n]     = E + O;
        o[7 - n] = E - O;
    }
    __stcs(reinterpret_cast<float4*>(dst),
           make_float4(o[0], o[1], o[2], o[3]));
    __stcs(reinterpret_cast<float4*>(dst + 4),
           make_float4(o[4], o[5], o[6], o[7]));
}

// Masked inverse DCT of one band, row pairs (m, 7-m):
// Dv(k,7-m) = (-1)^k Dv(k,m), so stage-1 even/odd-k partial sums are shared.
template <int BAND>
__device__ __forceinline__ void band_idct(const float C[8][8], float scale,
                                          float* __restrict__ dst)
{
#pragma unroll
    for (int m = 0; m < 4; m++) {
        float yA[8], yB[8];
#pragma unroll
        for (int l = 0; l < 8; l++) {
            if (col_active(BAND, l)) {
                float se = 0.0f, so = 0.0f;
#pragma unroll
                for (int k = 0; k < 8; k += 2)
                    if (in_band(BAND, k, l)) se = fmaf(C[k][l], Dv(k, m), se);
#pragma unroll
                for (int k = 1; k < 8; k += 2)
                    if (in_band(BAND, k, l)) so = fmaf(C[k][l], Dv(k, m), so);
                yA[l] = (se + so) * scale;   // row m
                yB[l] = (se - so) * scale;   // row 7-m
            } else {
                yA[l] = 0.0f; yB[l] = 0.0f;
            }
        }
        idct_row_store<BAND>(yA, dst + (size_t)m * W);
        idct_row_store<BAND>(yB, dst + (size_t)(7 - m) * W);
    }
}

__global__ void __launch_bounds__(TPB, 8)
dct_decomp_kernel(const float* __restrict__ x,
                  const float* __restrict__ band_scale,
                  float* __restrict__ out)
{
    const int tid = blockIdx.x * TPB + threadIdx.x;   // grid sized exactly
    const int bw = tid & 63;          // block col (W/8 = 64)
    const int bh = (tid >> 6) & 63;   // block row
    const int bc = tid >> 12;         // fused batch*chan

    const size_t base = ((size_t)bc * H + (size_t)bh * 8) * W + (size_t)bw * 8;
    const float* src = x + base;

    const float s0 = __ldg(band_scale + 0);
    const float s1 = __ldg(band_scale + 1);
    const float s2 = __ldg(band_scale + 2);

    // ---- Load 8x8 block (16 independent LDG.128, default caching:
    //      input stays L2-resident across graph replays) ----
    float C[8][8];
#pragma unroll
    for (int r = 0; r < 8; r++) {
        float4 a = __ldg(reinterpret_cast<const float4*>(src + (size_t)r * W));
        float4 b = __ldg(reinterpret_cast<const float4*>(src + (size_t)r * W + 4));
        C[r][0] = a.x; C[r][1] = a.y; C[r][2] = a.z; C[r][3] = a.w;
        C[r][4] = b.x; C[r][5] = b.y; C[r][6] = b.z; C[r][7] = b.w;
    }

    // ---- Forward 2D DCT in place: columns then rows, butterflied ----
#pragma unroll
    for (int t = 0; t < 8; t++) {
        float col[8];
#pragma unroll
        for (int m = 0; m < 8; m++) col[m] = C[m][t];
        dct8(col);
#pragma unroll
        for (int k = 0; k < 8; k++) C[k][t] = col[k];
    }
#pragma unroll
    for (int k = 0; k < 8; k++)
        dct8(C[k]);

    // ---- Three masked inverse DCTs ----
    band_idct<0>(C, s0, out + base);
    band_idct<1>(C, s1, out + (size_t)NPIX + base);
    band_idct<2>(C, s2, out + 2 * (size_t)NPIX + base);
}

extern "C" void kernel_launch(void* const* d_in, const int* in_sizes, int n_in,
                              void* d_out, int out_size)
{
    const float* x  = (const float*)d_in[0];
    const float* bs = (const float*)d_in[1];
    float* out = (float*)d_out;

    const int grid = NBLK / TPB;   // 1536
    dct_decomp_kernel<<<grid, TPB>>>(x, bs, out);
}

// round 10
// speedup vs baseline: 1.4635x; 1.1689x over previous
#include <cuda_runtime.h>

// DCT band decomposition: x[16,3,512,512] f32 -> (low, mid, high) concatenated.
// One thread per 8x8 block, TWO blocks per thread sequentially -> grid 768
// fits in ONE resident wave (148 SMs x 6 CTAs = 888): no wave-2 tail.
// Second block's lines are L2-prefetched up front. Butterfly forward DCT;
// band IDCTs use m/(7-m), n/(7-n) cosine symmetry; constants fold to FFMA imm.

namespace {
constexpr int H = 512, W = 512;
constexpr int NPIX = 16 * 3 * H * W;             // 12582912
constexpr int NBLK = 16 * 3 * (H / 8) * (W / 8); // 196608
constexpr int TPB  = 128;
constexpr int NTH  = NBLK / 2;                   // 98304 threads, 2 blocks each
}

#define A4f 0.3535533905932738f
#define C1f 0.4903926402016152f
#define C2f 0.4619397662556434f
#define C3f 0.4157348061512726f
#define C5f 0.2777851165098011f
#define C6f 0.1913417161825449f
#define C7f 0.0975451610080641f

__host__ __device__ constexpr float Dv(int k, int t) {
    constexpr float m[8][8] = {
        { A4f,  A4f,  A4f,  A4f,  A4f,  A4f,  A4f,  A4f},
        { C1f,  C3f,  C5f,  C7f, -C7f, -C5f, -C3f, -C1f},
        { C2f,  C6f, -C6f, -C2f, -C2f, -C6f,  C6f,  C2f},
        { C3f, -C7f, -C1f, -C5f,  C5f,  C1f,  C7f, -C3f},
        { A4f, -A4f, -A4f,  A4f,  A4f, -A4f, -A4f,  A4f},
        { C5f, -C1f,  C7f,  C3f, -C3f, -C7f,  C1f, -C5f},
        { C6f, -C2f,  C2f, -C6f, -C6f,  C2f, -C2f,  C6f},
        { C7f, -C5f,  C3f, -C1f,  C1f, -C3f,  C5f, -C7f}
    };
    return m[k][t];
}

// Zigzag bands: low = zz<21 <=> k+l<=5 ; mid = 21<=zz<42 <=> 6<=k+l<=8 \ (1,7)
__host__ __device__ constexpr bool in_band(int band, int k, int l) {
    const int s = k + l;
    const bool low = (s <= 5);
    const bool mid = (s >= 6 && s <= 8) && !(k == 1 && l == 7);
    if (band == 0) return low;
    if (band == 1) return mid;
    return !low && !mid;
}
__host__ __device__ constexpr bool col_active(int band, int l) {
    bool a = false;
    for (int k = 0; k < 8; k++) if (in_band(band, k, l)) a = true;
    return a;
}

// Fast 8-point DCT-II (orthonormal) in place.
__device__ __forceinline__ void dct8(float x[8]) {
    const float e0 = x[0] + x[7], e1 = x[1] + x[6], e2 = x[2] + x[5], e3 = x[3] + x[4];
    const float o0 = x[0] - x[7], o1 = x[1] - x[6], o2 = x[2] - x[5], o3 = x[3] - x[4];
    const float f0 = e0 + e3, f1 = e1 + e2;
    const float g0 = e0 - e3, g1 = e1 - e2;
    x[0] = A4f * (f0 + f1);
    x[4] = A4f * (f0 - f1);
    x[2] = fmaf(C2f, g0,  C6f * g1);
    x[6] = fmaf(C6f, g0, -C2f * g1);
    x[1] = fmaf(C1f, o0, fmaf( C3f, o1, fmaf( C5f, o2,  C7f * o3)));
    x[3] = fmaf(C3f, o0, fmaf(-C7f, o1, fmaf(-C1f, o2, -C5f * o3)));
    x[5] = fmaf(C5f, o0, fmaf(-C1f, o1, fmaf( C7f, o2,  C3f * o3)));
    x[7] = fmaf(C7f, o0, fmaf(-C5f, o1, fmaf( C3f, o2, -C1f * o3)));
}

template <int BAND>
__device__ __forceinline__ void idct_row_store(const float y[8],
                                               float* __restrict__ dst)
{
    float o[8];
#pragma unroll
    for (int n = 0; n < 4; n++) {
        float E = 0.0f, O = 0.0f;
#pragma unroll
        for (int l = 0; l < 8; l += 2)
            if (col_active(BAND, l)) E = fmaf(y[l], Dv(l, n), E);
#pragma unroll
        for (int l = 1; l < 8; l += 2)
            if (col_active(BAND, l)) O = fmaf(y[l], Dv(l, n), O);
        o[n]     = E + O;
        o[7 - n] = E - O;
    }
    __stcs(reinterpret_cast<float4*>(dst),
           make_float4(o[0], o[1], o[2], o[3]));
    __stcs(reinterpret_cast<float4*>(dst + 4),
           make_float4(o[4], o[5], o[6], o[7]));
}

template <int BAND>
__device__ __forceinline__ void band_idct(const float C[8][8], float scale,
                                          float* __restrict__ dst)
{
#pragma unroll
    for (int m = 0; m < 4; m++) {
        float yA[8], yB[8];
#pragma unroll
        for (int l = 0; l < 8; l++) {
            if (col_active(BAND, l)) {
                float se = 0.0f, so = 0.0f;
#pragma unroll
                for (int k = 0; k < 8; k += 2)
                    if (in_band(BAND, k, l)) se = fmaf(C[k][l], Dv(k, m), se);
#pragma unroll
                for (int k = 1; k < 8; k += 2)
                    if (in_band(BAND, k, l)) so = fmaf(C[k][l], Dv(k, m), so);
                yA[l] = (se + so) * scale;   // row m
                yB[l] = (se - so) * scale;   // row 7-m
            } else {
                yA[l] = 0.0f; yB[l] = 0.0f;
            }
        }
        idct_row_store<BAND>(yA, dst + (size_t)m * W);
        idct_row_store<BAND>(yB, dst + (size_t)(7 - m) * W);
    }
}

__device__ __forceinline__ size_t block_base(int tid) {
    const int bw = tid & 63;
    const int bh = (tid >> 6) & 63;
    const int bc = tid >> 12;
    return ((size_t)bc * H + (size_t)bh * 8) * W + (size_t)bw * 8;
}

__global__ void __launch_bounds__(TPB, 6)
dct_decomp_kernel(const float* __restrict__ x,
                  const float* __restrict__ band_scale,
                  float* __restrict__ out)
{
    const int t0 = blockIdx.x * TPB + threadIdx.x;   // [0, 98304)

    const float s0 = __ldg(band_scale + 0);
    const float s1 = __ldg(band_scale + 1);
    const float s2 = __ldg(band_scale + 2);

    // Prefetch second block's 8 cache lines into L2 (no data registers).
    {
        const float* p2 = x + block_base(t0 + NTH);
#pragma unroll
        for (int r = 0; r < 8; r++)
            asm volatile("prefetch.global.L2 [%0];"
                         :: "l"(p2 + (size_t)r * W));
    }

#pragma unroll 1
    for (int it = 0; it < 2; it++) {
        const int tid = t0 + it * NTH;
        const size_t base = block_base(tid);
        const float* src = x + base;

        // ---- Load 8x8 block (16 LDG.128, front-batched) ----
        float C[8][8];
#pragma unroll
        for (int r = 0; r < 8; r++) {
            float4 a = __ldg(reinterpret_cast<const float4*>(src + (size_t)r * W));
            float4 b = __ldg(reinterpret_cast<const float4*>(src + (size_t)r * W + 4));
            C[r][0] = a.x; C[r][1] = a.y; C[r][2] = a.z; C[r][3] = a.w;
            C[r][4] = b.x; C[r][5] = b.y; C[r][6] = b.z; C[r][7] = b.w;
        }

        // ---- Forward 2D DCT in place: columns then rows ----
#pragma unroll
        for (int t = 0; t < 8; t++) {
            float col[8];
#pragma unroll
            for (int m = 0; m < 8; m++) col[m] = C[m][t];
            dct8(col);
#pragma unroll
            for (int k = 0; k < 8; k++) C[k][t] = col[k];
        }
#pragma unroll
        for (int k = 0; k < 8; k++)
            dct8(C[k]);

        // ---- Three masked inverse DCTs ----
        band_idct<0>(C, s0, out + base);
        band_idct<1>(C, s1, out + (size_t)NPIX + base);
        band_idct<2>(C, s2, out + 2 * (size_t)NPIX + base);
    }
}

extern "C" void kernel_launch(void* const* d_in, const int* in_sizes, int n_in,
                              void* d_out, int out_size)
{
    const float* x  = (const float*)d_in[0];
    const float* bs = (const float*)d_in[1];
    float* out = (float*)d_out;

    const int grid = NTH / TPB;   // 768 CTAs -> single resident wave
    dct_decomp_kernel<<<grid, TPB>>>(x, bs, out);
}